// round 10
// baseline (speedup 1.0000x reference)
#include <cuda_runtime.h>
#include <cuda_fp16.h>
#include <cstdint>

// Problem constants (fixed by setup_inputs)
#define B_    4
#define NC    4096      // coarse points per batch
#define MF    16384     // fine points per batch
#define CIN   384
#define COUT  192
#define NTOT  (B_*NC)   // 16384
#define MTOT  (B_*MF)   // 65536

// Scratch (static device globals; allocation-free)
__device__ float g_h[NTOT * COUT];          // branch-2 features at coarse points
__device__ int   g_idx[MTOT * 3];           // 3-NN indices
__device__ float g_wgt[MTOT * 3];           // 3-NN inverse-distance weights
__device__ float g_stat_f[NTOT * 2];        // per-row (mu, rstd) feats (for SIMT gemm2)
__device__ __align__(16) __half g_shi[MTOT * COUT];  // LN(sfeats) fp16 hi/lo
__device__ __align__(16) __half g_slo[MTOT * COUT];
__device__ float g_w2p[CIN * COUT];         // gamma-folded w2, fp32 [k][n] (SIMT)
__device__ __align__(16) __half g_w1h[COUT * COUT];  // gamma-folded w1, fp16, transposed [N][K]
__device__ float g_b2p[COUT];               // beta-folded biases
__device__ float g_b1p[COUT];

// ---------------------------------------------------------------------------
// PTX helpers (baseline PTX, sm_80+: valid on compute_103 target)
// ---------------------------------------------------------------------------
__device__ __forceinline__ void ldsm4(uint32_t* r, uint32_t addr) {
    asm volatile("ldmatrix.sync.aligned.m8n8.x4.shared.b16 {%0,%1,%2,%3}, [%4];"
                 : "=r"(r[0]), "=r"(r[1]), "=r"(r[2]), "=r"(r[3]) : "r"(addr));
}
__device__ __forceinline__ void mma16816h(float* d, const uint32_t* a, const uint32_t* b) {
    asm volatile("mma.sync.aligned.m16n8k16.row.col.f32.f16.f16.f32 "
                 "{%0,%1,%2,%3}, {%4,%5,%6,%7}, {%8,%9}, {%0,%1,%2,%3};"
                 : "+f"(d[0]), "+f"(d[1]), "+f"(d[2]), "+f"(d[3])
                 : "r"(a[0]), "r"(a[1]), "r"(a[2]), "r"(a[3]), "r"(b[0]), "r"(b[1]));
}
__device__ __forceinline__ void cp_async16(uint32_t saddr, const void* gptr) {
    asm volatile("cp.async.cg.shared.global [%0], [%1], 16;" :: "r"(saddr), "l"(gptr));
}
__device__ __forceinline__ void cp_commit() { asm volatile("cp.async.commit_group;"); }
__device__ __forceinline__ void cp_wait1()  { asm volatile("cp.async.wait_group 1;" ::: "memory"); }
__device__ __forceinline__ void cp_wait0()  { asm volatile("cp.async.wait_group 0;" ::: "memory"); }
__device__ __forceinline__ uint32_t sw128(uint32_t off) { return off ^ ((off >> 3) & 0x70); }
__device__ __forceinline__ uint32_t smem_addr(const void* p) {
    return (uint32_t)__cvta_generic_to_shared(p);
}

// ---------------------------------------------------------------------------
// Per-row LN statistics only (fp32), for the SIMT gemm. One warp per row.
// ---------------------------------------------------------------------------
template<int C>
__global__ void stats_kernel(const float* __restrict__ x, float* __restrict__ stat, int rows)
{
    int warp = (blockIdx.x * blockDim.x + threadIdx.x) >> 5;
    if (warp >= rows) return;
    int lane = threadIdx.x & 31;
    const float* xr = x + (long)warp * C;
    float s = 0.f, ss = 0.f;
#pragma unroll
    for (int i = 0; i < C / 32; i++) {
        float v = xr[lane + i * 32];
        s += v;
        ss += v * v;
    }
#pragma unroll
    for (int o = 16; o; o >>= 1) {
        s  += __shfl_xor_sync(0xffffffffu, s,  o);
        ss += __shfl_xor_sync(0xffffffffu, ss, o);
    }
    if (lane == 0) {
        float mu  = s * (1.0f / C);
        float var = ss * (1.0f / C) - mu * mu;
        stat[warp * 2 + 0] = mu;
        stat[warp * 2 + 1] = rsqrtf(var + 1e-5f);
    }
}

// ---------------------------------------------------------------------------
// Fused LN stats + normalize + fp16 hi/lo split. One warp per row.
// ---------------------------------------------------------------------------
template<int C>
__global__ void stats_conv16_kernel(const float* __restrict__ x,
                                    __half* __restrict__ hi,
                                    __half* __restrict__ lo, int rows)
{
    int row = (blockIdx.x * blockDim.x + threadIdx.x) >> 5;
    if (row >= rows) return;
    int lane = threadIdx.x & 31;
    const float4* xr = (const float4*)(x + (long)row * C);

    float s = 0.f, ss = 0.f;
    for (int j = lane; j < C / 4; j += 32) {
        float4 v = xr[j];
        s  += v.x + v.y + v.z + v.w;
        ss += v.x * v.x + v.y * v.y + v.z * v.z + v.w * v.w;
    }
#pragma unroll
    for (int o = 16; o; o >>= 1) {
        s  += __shfl_xor_sync(0xffffffffu, s,  o);
        ss += __shfl_xor_sync(0xffffffffu, ss, o);
    }
    float mu   = s * (1.0f / C);
    float var  = ss * (1.0f / C) - mu * mu;
    float rstd = rsqrtf(var + 1e-5f);

    uint2* hrow = (uint2*)(hi + (long)row * C);
    uint2* lrow = (uint2*)(lo + (long)row * C);
    for (int j = lane; j < C / 4; j += 32) {
        float4 v = xr[j];
        float vv[4] = {(v.x - mu) * rstd, (v.y - mu) * rstd,
                       (v.z - mu) * rstd, (v.w - mu) * rstd};
        union { __half h[4]; uint2 u; } hh, ll;
#pragma unroll
        for (int q = 0; q < 4; q++) {
            __half hb = __float2half_rn(vv[q]);
            hh.h[q] = hb;
            ll.h[q] = __float2half_rn(vv[q] - __half2float(hb));
        }
        hrow[j] = hh.u;
        lrow[j] = ll.u;
    }
}

// ---------------------------------------------------------------------------
// Prep: w2 -> fp32 folded [k][n] (SIMT gemm2); w1 -> fp16 folded transposed
// [N][K] (mma gemm1); beta-folded biases.
// grid = CIN + COUT + 2 blocks, 192 threads.
// ---------------------------------------------------------------------------
__global__ void prep_kernel(const float* __restrict__ w2, const float* __restrict__ ln2_g,
                            const float* __restrict__ ln2_b, const float* __restrict__ b2,
                            const float* __restrict__ w1, const float* __restrict__ ln1_g,
                            const float* __restrict__ ln1_b, const float* __restrict__ b1)
{
    int bid = blockIdx.x;
    int t = threadIdx.x;
    if (bid < CIN) {                          // w2 row k (fp32 folded)
        g_w2p[bid * COUT + t] = ln2_g[bid] * w2[bid * COUT + t];
    } else if (bid < CIN + COUT) {            // w1 col n -> fp16 transposed row n
        int n = bid - CIN;
        for (int k = t; k < COUT; k += COUT)
            g_w1h[n * COUT + k] = __float2half_rn(ln1_g[k] * w1[k * COUT + n]);
    } else if (bid == CIN + COUT) {
        float s = b2[t];
        for (int k = 0; k < CIN; k++) s = fmaf(ln2_b[k], w2[k * COUT + t], s);
        g_b2p[t] = s;
    } else {
        float s = b1[t];
        for (int k = 0; k < COUT; k++) s = fmaf(ln1_b[k], w1[k * COUT + t], s);
        g_b1p[t] = s;
    }
}

// ---------------------------------------------------------------------------
// Brute-force 3-NN. 2 queries per thread, 512 queries per block.
// ---------------------------------------------------------------------------
__global__ void knn_kernel(const float* __restrict__ cxyz, const float* __restrict__ qxyz)
{
    extern __shared__ char smem_c[];
    float* sx = (float*)smem_c;
    float* sy = sx + NC;
    float* sz = sx + 2 * NC;

    int bidx  = blockIdx.x >> 5;
    int chunk = blockIdx.x & 31;
    const float* cb = cxyz + (long)bidx * NC * 3;
    for (int i = threadIdx.x; i < NC; i += 256) {
        sx[i] = cb[i * 3 + 0];
        sy[i] = cb[i * 3 + 1];
        sz[i] = cb[i * 3 + 2];
    }
    __syncthreads();

    int qA = bidx * MF + chunk * 512 + threadIdx.x;
    int qB = qA + 256;
    float ax = qxyz[qA * 3 + 0], ay = qxyz[qA * 3 + 1], az = qxyz[qA * 3 + 2];
    float bx = qxyz[qB * 3 + 0], by = qxyz[qB * 3 + 1], bz = qxyz[qB * 3 + 2];

    float a0 = 1e30f, a1 = 1e30f, a2 = 1e30f; int ai0 = 0, ai1 = 0, ai2 = 0;
    float c0 = 1e30f, c1 = 1e30f, c2 = 1e30f; int ci0 = 0, ci1 = 0, ci2 = 0;

#pragma unroll 8
    for (int j = 0; j < NC; j++) {
        float px = sx[j], py = sy[j], pz = sz[j];
        {
            float dx = ax - px, dy = ay - py, dz = az - pz;
            float d = fmaf(dz, dz, fmaf(dy, dy, dx * dx));
            if (d < a2) {
                if (d < a1) {
                    a2 = a1; ai2 = ai1;
                    if (d < a0) { a1 = a0; ai1 = ai0; a0 = d; ai0 = j; }
                    else        { a1 = d;  ai1 = j; }
                } else { a2 = d; ai2 = j; }
            }
        }
        {
            float dx = bx - px, dy = by - py, dz = bz - pz;
            float d = fmaf(dz, dz, fmaf(dy, dy, dx * dx));
            if (d < c2) {
                if (d < c1) {
                    c2 = c1; ci2 = ci1;
                    if (d < c0) { c1 = c0; ci1 = ci0; c0 = d; ci0 = j; }
                    else        { c1 = d;  ci1 = j; }
                } else { c2 = d; ci2 = j; }
            }
        }
    }

    {
        float r0 = 1.0f / (sqrtf(a0) + 1e-8f);
        float r1 = 1.0f / (sqrtf(a1) + 1e-8f);
        float r2 = 1.0f / (sqrtf(a2) + 1e-8f);
        float rs = 1.0f / (r0 + r1 + r2);
        g_idx[qA * 3 + 0] = bidx * NC + ai0;
        g_idx[qA * 3 + 1] = bidx * NC + ai1;
        g_idx[qA * 3 + 2] = bidx * NC + ai2;
        g_wgt[qA * 3 + 0] = r0 * rs;
        g_wgt[qA * 3 + 1] = r1 * rs;
        g_wgt[qA * 3 + 2] = r2 * rs;
    }
    {
        float r0 = 1.0f / (sqrtf(c0) + 1e-8f);
        float r1 = 1.0f / (sqrtf(c1) + 1e-8f);
        float r2 = 1.0f / (sqrtf(c2) + 1e-8f);
        float rs = 1.0f / (r0 + r1 + r2);
        g_idx[qB * 3 + 0] = bidx * NC + ci0;
        g_idx[qB * 3 + 1] = bidx * NC + ci1;
        g_idx[qB * 3 + 2] = bidx * NC + ci2;
        g_wgt[qB * 3 + 0] = r0 * rs;
        g_wgt[qB * 3 + 1] = r1 * rs;
        g_wgt[qB * 3 + 2] = r2 * rs;
    }
}

// ---------------------------------------------------------------------------
// SIMT fp32 fused LN+GEMM (proven R2 kernel): g_h = LN(feats)@w2' + b2'.
// BM=128, BN=64, BK=16, 256 threads, 8x4 microtile, double-buffered.
// ---------------------------------------------------------------------------
template<int K>
__global__ __launch_bounds__(256)
void gemm_simt(const float* __restrict__ A, const float* __restrict__ stat,
               const float* __restrict__ W, const float* __restrict__ bias,
               float* __restrict__ C)
{
    constexpr int KT = K / 16;
    __shared__ float As[2][16][132];
    __shared__ float Bs[2][16][68];

    int t  = threadIdx.x;
    int tx = t & 15, ty = t >> 4;
    int m0 = blockIdx.y * 128;
    int n0 = blockIdx.x * 64;

    int arow  = t >> 1;
    int acol8 = (t & 1) * 8;
    const float* Arow = A + (long)(m0 + arow) * K;
    float mu   = stat[(m0 + arow) * 2 + 0];
    float rstd = stat[(m0 + arow) * 2 + 1];

    int brow = t >> 4;
    int bcol = (t & 15) * 4;

    float4 pa0, pa1, pb;
    pa0 = *(const float4*)(Arow + acol8);
    pa1 = *(const float4*)(Arow + acol8 + 4);
    pb  = *(const float4*)(W + (long)brow * COUT + n0 + bcol);
    As[0][acol8 + 0][arow] = (pa0.x - mu) * rstd;
    As[0][acol8 + 1][arow] = (pa0.y - mu) * rstd;
    As[0][acol8 + 2][arow] = (pa0.z - mu) * rstd;
    As[0][acol8 + 3][arow] = (pa0.w - mu) * rstd;
    As[0][acol8 + 4][arow] = (pa1.x - mu) * rstd;
    As[0][acol8 + 5][arow] = (pa1.y - mu) * rstd;
    As[0][acol8 + 6][arow] = (pa1.z - mu) * rstd;
    As[0][acol8 + 7][arow] = (pa1.w - mu) * rstd;
    *(float4*)&Bs[0][brow][bcol] = pb;
    __syncthreads();

    float acc[8][4] = {};
    int s = 0;

#pragma unroll 1
    for (int kt = 0; kt < KT; kt++) {
        int k0n = (kt + 1) * 16;
        if (kt + 1 < KT) {
            pa0 = *(const float4*)(Arow + k0n + acol8);
            pa1 = *(const float4*)(Arow + k0n + acol8 + 4);
            pb  = *(const float4*)(W + (long)(k0n + brow) * COUT + n0 + bcol);
        }
#pragma unroll
        for (int k = 0; k < 16; k++) {
            float4 a0 = *(const float4*)&As[s][k][ty * 8];
            float4 a1 = *(const float4*)&As[s][k][ty * 8 + 4];
            float4 b  = *(const float4*)&Bs[s][k][tx * 4];
            float ar[8] = {a0.x, a0.y, a0.z, a0.w, a1.x, a1.y, a1.z, a1.w};
            float br[4] = {b.x, b.y, b.z, b.w};
#pragma unroll
            for (int i = 0; i < 8; i++)
#pragma unroll
                for (int j = 0; j < 4; j++)
                    acc[i][j] = fmaf(ar[i], br[j], acc[i][j]);
        }
        if (kt + 1 < KT) {
            int ns = s ^ 1;
            As[ns][acol8 + 0][arow] = (pa0.x - mu) * rstd;
            As[ns][acol8 + 1][arow] = (pa0.y - mu) * rstd;
            As[ns][acol8 + 2][arow] = (pa0.z - mu) * rstd;
            As[ns][acol8 + 3][arow] = (pa0.w - mu) * rstd;
            As[ns][acol8 + 4][arow] = (pa1.x - mu) * rstd;
            As[ns][acol8 + 5][arow] = (pa1.y - mu) * rstd;
            As[ns][acol8 + 6][arow] = (pa1.z - mu) * rstd;
            As[ns][acol8 + 7][arow] = (pa1.w - mu) * rstd;
            *(float4*)&Bs[ns][brow][bcol] = pb;
            __syncthreads();
            s = ns;
        }
    }

    float bb[4];
#pragma unroll
    for (int j = 0; j < 4; j++) bb[j] = bias[n0 + tx * 4 + j];

#pragma unroll
    for (int i = 0; i < 8; i++) {
        int row = m0 + ty * 8 + i;
        float4 o = make_float4(acc[i][0] + bb[0], acc[i][1] + bb[1],
                               acc[i][2] + bb[2], acc[i][3] + bb[3]);
        *(float4*)(C + (long)row * COUT + n0 + tx * 4) = o;
    }
}

// ---------------------------------------------------------------------------
// fp16 2-term warp-MMA GEMM:  out = (Ahi+Alo)[M,K] @ Wh[K,192] + b'
// CTA 128x64, 8 warps (4Mx2N), warp tile 32x32, BK=64, 2-stage cp.async.
// D = Ahi*W + Alo*W (W single fp16; A exact to ~2^-22).
// ---------------------------------------------------------------------------
#define HA_HI  0
#define HA_LO  16384
#define HB     32768
#define HSTRIDE 40960
#define HSMEM   (2 * HSTRIDE)

template<int K>
__global__ __launch_bounds__(256)
void mma_gemm16(const __half* __restrict__ Ahi, const __half* __restrict__ Alo,
                const __half* __restrict__ Wh, const float* __restrict__ bias,
                float* __restrict__ C)
{
    constexpr int KT = K / 64;
    extern __shared__ char smem_c[];

    const int t    = threadIdx.x;
    const int lane = t & 31;
    const int wid  = t >> 5;
    const int wm   = wid & 3;
    const int wn   = wid >> 2;
    const int m0   = blockIdx.y * 128;
    const int n0   = blockIdx.x * 64;
    const int g8   = lane >> 3, r8 = lane & 7;
    const uint32_t sm0 = smem_addr(smem_c);

    int arow[4], akc[4]; uint32_t aoff[4];
#pragma unroll
    for (int q = 0; q < 4; q++) {
        int c = t + 256 * q;
        arow[q] = c >> 3;
        akc[q]  = (c & 7) * 8;
        aoff[q] = sw128((uint32_t)(arow[q] * 128 + (c & 7) * 16));
    }
    int brow[2], bkc[2]; uint32_t boff[2];
#pragma unroll
    for (int q = 0; q < 2; q++) {
        int c = t + 256 * q;
        brow[q] = c >> 3;
        bkc[q]  = (c & 7) * 8;
        boff[q] = sw128((uint32_t)(brow[q] * 128 + (c & 7) * 16));
    }

    auto issue = [&](int stage, int k0) {
        uint32_t sb = sm0 + (uint32_t)stage * HSTRIDE;
#pragma unroll
        for (int q = 0; q < 4; q++) {
            long src = (long)(m0 + arow[q]) * K + k0 + akc[q];
            cp_async16(sb + HA_HI + aoff[q], Ahi + src);
            cp_async16(sb + HA_LO + aoff[q], Alo + src);
        }
#pragma unroll
        for (int q = 0; q < 2; q++) {
            long src = (long)(n0 + brow[q]) * K + k0 + bkc[q];
            cp_async16(sb + HB + boff[q], Wh + src);
        }
        cp_commit();
    };

    issue(0, 0);

    float d[2][4][4] = {};

#pragma unroll 1
    for (int kt = 0; kt < KT; kt++) {
        const int cur  = kt & 1;
        const bool more = (kt + 1 < KT);
        if (more) issue(cur ^ 1, (kt + 1) * 64);
        if (more) cp_wait1(); else cp_wait0();
        __syncthreads();

        const uint32_t sbase = sm0 + (uint32_t)cur * HSTRIDE;
#pragma unroll
        for (int ks = 0; ks < 4; ks++) {
            const int kb = ks * 16;
            uint32_t ah[2][4], al[2][4], bh[2][4];
#pragma unroll
            for (int mi = 0; mi < 2; mi++) {
                int row = wm * 32 + mi * 16 + (g8 & 1) * 8 + r8;
                int kc  = kb + (g8 >> 1) * 8;
                uint32_t ad = sbase + sw128((uint32_t)(row * 128 + kc * 2));
                ldsm4(ah[mi], ad + HA_HI);
                ldsm4(al[mi], ad + HA_LO);
            }
#pragma unroll
            for (int ni = 0; ni < 2; ni++) {
                int row = wn * 32 + ni * 16 + (g8 >> 1) * 8 + r8;
                int kc  = kb + (g8 & 1) * 8;
                uint32_t bd = sbase + sw128((uint32_t)(row * 128 + kc * 2));
                ldsm4(bh[ni], bd + HB);
            }
#pragma unroll
            for (int mi = 0; mi < 2; mi++)
#pragma unroll
                for (int ni = 0; ni < 2; ni++)
#pragma unroll
                    for (int h = 0; h < 2; h++) {
                        float* acc = d[mi][ni * 2 + h];
                        mma16816h(acc, ah[mi], &bh[ni][h * 2]);
                        mma16816h(acc, al[mi], &bh[ni][h * 2]);
                    }
        }
        if (more) __syncthreads();
    }

    // epilogue: bias only (interp added later by interp_add)
    const int lr = lane >> 2;
    const int lc = (lane & 3) * 2;
#pragma unroll
    for (int mi = 0; mi < 2; mi++) {
#pragma unroll
        for (int half = 0; half < 2; half++) {
            int row = m0 + wm * 32 + mi * 16 + lr + half * 8;
            float* crow = C + (long)row * COUT;
#pragma unroll
            for (int nt = 0; nt < 4; nt++) {
                int col = n0 + wn * 32 + nt * 8 + lc;
                float vx = d[mi][nt][half * 2 + 0] + bias[col + 0];
                float vy = d[mi][nt][half * 2 + 1] + bias[col + 1];
                *(float2*)(crow + col) = make_float2(vx, vy);
            }
        }
    }
}

// ---------------------------------------------------------------------------
// interp_add: out[row] += w0*g_h[j0] + w1*g_h[j1] + w2*g_h[j2]
// 192 threads/block (thread = column), 16 rows per block.
// ---------------------------------------------------------------------------
__global__ void interp_add_kernel(float* __restrict__ out)
{
    int col = threadIdx.x;
#pragma unroll 1
    for (int r = 0; r < 16; r++) {
        int row = blockIdx.x * 16 + r;
        int   j0 = g_idx[row * 3 + 0], j1 = g_idx[row * 3 + 1], j2 = g_idx[row * 3 + 2];
        float w0 = g_wgt[row * 3 + 0], w1 = g_wgt[row * 3 + 1], w2 = g_wgt[row * 3 + 2];
        float v = w0 * g_h[(long)j0 * COUT + col]
                + w1 * g_h[(long)j1 * COUT + col]
                + w2 * g_h[(long)j2 * COUT + col];
        out[(long)row * COUT + col] += v;
    }
}

// ---------------------------------------------------------------------------
// Tail: copy support_xyz and support_offset (value-cast to float) into d_out
// ---------------------------------------------------------------------------
__global__ void tail_kernel(const float* __restrict__ sxyz, const int* __restrict__ soff,
                            float* __restrict__ out)
{
    int i = blockIdx.x * 256 + threadIdx.x;
    if (i < MTOT * 3) out[MTOT * COUT + i] = sxyz[i];
    if (i < B_)       out[MTOT * COUT + MTOT * 3 + i] = (float)soff[i];
}

// ---------------------------------------------------------------------------
extern "C" void kernel_launch(void* const* d_in, const int* in_sizes, int n_in,
                              void* d_out, int out_size)
{
    const float* feats  = (const float*)d_in[0];
    const float* xyz    = (const float*)d_in[1];
    const float* sxyz   = (const float*)d_in[2];
    const float* sfeats = (const float*)d_in[3];
    const int*   soff   = (const int*)  d_in[5];
    const float* ln1_g  = (const float*)d_in[6];
    const float* ln1_b  = (const float*)d_in[7];
    const float* w1     = (const float*)d_in[8];
    const float* b1     = (const float*)d_in[9];
    const float* ln2_g  = (const float*)d_in[10];
    const float* ln2_b  = (const float*)d_in[11];
    const float* w2     = (const float*)d_in[12];
    const float* b2     = (const float*)d_in[13];
    float* out = (float*)d_out;

    static cudaStream_t s2 = nullptr, s3 = nullptr;
    static cudaEvent_t ev_fork = nullptr, ev_j2 = nullptr, ev_j3 = nullptr, ev_prep = nullptr;
    static bool attr_done = false;
    if (!s2) {
        cudaStreamCreateWithFlags(&s2, cudaStreamNonBlocking);
        cudaStreamCreateWithFlags(&s3, cudaStreamNonBlocking);
        cudaEventCreateWithFlags(&ev_fork, cudaEventDisableTiming);
        cudaEventCreateWithFlags(&ev_j2, cudaEventDisableTiming);
        cudaEventCreateWithFlags(&ev_j3, cudaEventDisableTiming);
        cudaEventCreateWithFlags(&ev_prep, cudaEventDisableTiming);
    }
    if (!attr_done) {
        cudaFuncSetAttribute(mma_gemm16<COUT>, cudaFuncAttributeMaxDynamicSharedMemorySize, HSMEM);
        attr_done = true;
    }

    float *p_stat_f, *p_h, *p_w2p, *p_b2p, *p_b1p;
    __half *p_shi, *p_slo, *p_w1h;
    cudaGetSymbolAddress((void**)&p_stat_f, g_stat_f);
    cudaGetSymbolAddress((void**)&p_h,    g_h);
    cudaGetSymbolAddress((void**)&p_w2p,  g_w2p);
    cudaGetSymbolAddress((void**)&p_b2p,  g_b2p);
    cudaGetSymbolAddress((void**)&p_b1p,  g_b1p);
    cudaGetSymbolAddress((void**)&p_shi,  g_shi);
    cudaGetSymbolAddress((void**)&p_slo,  g_slo);
    cudaGetSymbolAddress((void**)&p_w1h,  g_w1h);

    // fork
    cudaEventRecord(ev_fork, 0);
    cudaStreamWaitEvent(s2, ev_fork, 0);
    cudaStreamWaitEvent(s3, ev_fork, 0);

    // s2: kNN + tail (independent)
    knn_kernel<<<MTOT / 512, 256, 3 * NC * sizeof(float), s2>>>(xyz, sxyz);
    tail_kernel<<<(MTOT * 3 + 255) / 256, 256, 0, s2>>>(sxyz, soff, out);
    cudaEventRecord(ev_j2, s2);

    // s3: prep -> sfeats fp16 conversion -> gemm1 (fp16 mma, tensor pipe) -> out
    prep_kernel<<<CIN + COUT + 2, COUT, 0, s3>>>(w2, ln2_g, ln2_b, b2, w1, ln1_g, ln1_b, b1);
    cudaEventRecord(ev_prep, s3);
    stats_conv16_kernel<COUT><<<MTOT / 8, 256, 0, s3>>>(sfeats, p_shi, p_slo, MTOT);
    {
        dim3 grid(COUT / 64, MTOT / 128);
        mma_gemm16<COUT><<<grid, 256, HSMEM, s3>>>(p_shi, p_slo, p_w1h, p_b1p, out);
    }
    cudaEventRecord(ev_j3, s3);

    // main: feats stats -> gemm2 (fp32 SIMT, fma pipe) -> g_h  (concurrent w/ s3)
    stats_kernel<CIN><<<NTOT / 8, 256>>>(feats, p_stat_f, NTOT);
    cudaStreamWaitEvent(0, ev_prep, 0);
    {
        dim3 grid(COUT / 64, NTOT / 128);
        gemm_simt<CIN><<<grid, 256>>>(feats, p_stat_f, p_w2p, p_b2p, p_h);
    }

    // join all, then fused interp add into out
    cudaStreamWaitEvent(0, ev_j2, 0);
    cudaStreamWaitEvent(0, ev_j3, 0);
    interp_add_kernel<<<MTOT / 16, COUT>>>(out);
}

// round 11
// speedup vs baseline: 1.0315x; 1.0315x over previous
#include <cuda_runtime.h>
#include <cuda_fp16.h>
#include <cstdint>

// Problem constants (fixed by setup_inputs)
#define B_    4
#define NC    4096      // coarse points per batch
#define MF    16384     // fine points per batch
#define CIN   384
#define COUT  192
#define NTOT  (B_*NC)   // 16384
#define MTOT  (B_*MF)   // 65536

// Scratch (static device globals; allocation-free)
__device__ float g_h[NTOT * COUT];          // branch-2 features at coarse points
__device__ int   g_idx[MTOT * 3];           // 3-NN indices
__device__ float g_wgt[MTOT * 3];           // 3-NN inverse-distance weights
__device__ __align__(16) __half g_fhi[NTOT * CIN];   // LN(feats) fp16 hi/lo
__device__ __align__(16) __half g_flo[NTOT * CIN];
__device__ __align__(16) __half g_shi[MTOT * COUT];  // LN(sfeats) fp16 hi/lo
__device__ __align__(16) __half g_slo[MTOT * COUT];
__device__ __align__(16) __half g_w2h[COUT * CIN];   // gamma-folded, fp16, transposed [N][K]
__device__ __align__(16) __half g_w1h[COUT * COUT];
__device__ float g_b2p[COUT];               // beta-folded biases
__device__ float g_b1p[COUT];

// ---------------------------------------------------------------------------
// PTX helpers (baseline PTX, sm_80+: valid on compute_103 target)
// ---------------------------------------------------------------------------
__device__ __forceinline__ void ldsm4(uint32_t* r, uint32_t addr) {
    asm volatile("ldmatrix.sync.aligned.m8n8.x4.shared.b16 {%0,%1,%2,%3}, [%4];"
                 : "=r"(r[0]), "=r"(r[1]), "=r"(r[2]), "=r"(r[3]) : "r"(addr));
}
__device__ __forceinline__ void mma16816h(float* d, const uint32_t* a, const uint32_t* b) {
    asm volatile("mma.sync.aligned.m16n8k16.row.col.f32.f16.f16.f32 "
                 "{%0,%1,%2,%3}, {%4,%5,%6,%7}, {%8,%9}, {%0,%1,%2,%3};"
                 : "+f"(d[0]), "+f"(d[1]), "+f"(d[2]), "+f"(d[3])
                 : "r"(a[0]), "r"(a[1]), "r"(a[2]), "r"(a[3]), "r"(b[0]), "r"(b[1]));
}
__device__ __forceinline__ void cp_async16(uint32_t saddr, const void* gptr) {
    asm volatile("cp.async.cg.shared.global [%0], [%1], 16;" :: "r"(saddr), "l"(gptr));
}
__device__ __forceinline__ void cp_commit() { asm volatile("cp.async.commit_group;"); }
__device__ __forceinline__ void cp_wait1()  { asm volatile("cp.async.wait_group 1;" ::: "memory"); }
__device__ __forceinline__ void cp_wait0()  { asm volatile("cp.async.wait_group 0;" ::: "memory"); }
__device__ __forceinline__ uint32_t sw128(uint32_t off) { return off ^ ((off >> 3) & 0x70); }
__device__ __forceinline__ uint32_t smem_addr(const void* p) {
    return (uint32_t)__cvta_generic_to_shared(p);
}

// ---------------------------------------------------------------------------
// Fused LN stats + normalize + fp16 hi/lo split. One warp per row.
// ---------------------------------------------------------------------------
template<int C>
__global__ void stats_conv16_kernel(const float* __restrict__ x,
                                    __half* __restrict__ hi,
                                    __half* __restrict__ lo, int rows)
{
    int row = (blockIdx.x * blockDim.x + threadIdx.x) >> 5;
    if (row >= rows) return;
    int lane = threadIdx.x & 31;
    const float4* xr = (const float4*)(x + (long)row * C);

    float s = 0.f, ss = 0.f;
    for (int j = lane; j < C / 4; j += 32) {
        float4 v = xr[j];
        s  += v.x + v.y + v.z + v.w;
        ss += v.x * v.x + v.y * v.y + v.z * v.z + v.w * v.w;
    }
#pragma unroll
    for (int o = 16; o; o >>= 1) {
        s  += __shfl_xor_sync(0xffffffffu, s,  o);
        ss += __shfl_xor_sync(0xffffffffu, ss, o);
    }
    float mu   = s * (1.0f / C);
    float var  = ss * (1.0f / C) - mu * mu;
    float rstd = rsqrtf(var + 1e-5f);

    uint2* hrow = (uint2*)(hi + (long)row * C);
    uint2* lrow = (uint2*)(lo + (long)row * C);
    for (int j = lane; j < C / 4; j += 32) {
        float4 v = xr[j];
        float vv[4] = {(v.x - mu) * rstd, (v.y - mu) * rstd,
                       (v.z - mu) * rstd, (v.w - mu) * rstd};
        union { __half h[4]; uint2 u; } hh, ll;
#pragma unroll
        for (int q = 0; q < 4; q++) {
            __half hb = __float2half_rn(vv[q]);
            hh.h[q] = hb;
            ll.h[q] = __float2half_rn(vv[q] - __half2float(hb));
        }
        hrow[j] = hh.u;
        lrow[j] = ll.u;
    }
}

// ---------------------------------------------------------------------------
// Prep: fold LN gamma into W (fp16, transposed [N][K]) and beta into bias.
// grid = 2*COUT + 2 blocks, 192 threads.
// ---------------------------------------------------------------------------
__global__ void prep_kernel(const float* __restrict__ w2, const float* __restrict__ ln2_g,
                            const float* __restrict__ ln2_b, const float* __restrict__ b2,
                            const float* __restrict__ w1, const float* __restrict__ ln1_g,
                            const float* __restrict__ ln1_b, const float* __restrict__ b1)
{
    int bid = blockIdx.x;
    int t = threadIdx.x;
    if (bid < COUT) {                         // w2 col n -> fp16 row n, K=CIN
        int n = bid;
        for (int k = t; k < CIN; k += COUT)
            g_w2h[n * CIN + k] = __float2half_rn(ln2_g[k] * w2[k * COUT + n]);
    } else if (bid < 2 * COUT) {              // w1 col n -> fp16 row n, K=COUT
        int n = bid - COUT;
        for (int k = t; k < COUT; k += COUT)
            g_w1h[n * COUT + k] = __float2half_rn(ln1_g[k] * w1[k * COUT + n]);
    } else if (bid == 2 * COUT) {
        float s = b2[t];
        for (int k = 0; k < CIN; k++) s = fmaf(ln2_b[k], w2[k * COUT + t], s);
        g_b2p[t] = s;
    } else {
        float s = b1[t];
        for (int k = 0; k < COUT; k++) s = fmaf(ln1_b[k], w1[k * COUT + t], s);
        g_b1p[t] = s;
    }
}

// ---------------------------------------------------------------------------
// Brute-force 3-NN. 2 queries per thread, 512 queries per block.
// ---------------------------------------------------------------------------
__global__ void knn_kernel(const float* __restrict__ cxyz, const float* __restrict__ qxyz)
{
    extern __shared__ char smem_c[];
    float* sx = (float*)smem_c;
    float* sy = sx + NC;
    float* sz = sx + 2 * NC;

    int bidx  = blockIdx.x >> 5;
    int chunk = blockIdx.x & 31;
    const float* cb = cxyz + (long)bidx * NC * 3;
    for (int i = threadIdx.x; i < NC; i += 256) {
        sx[i] = cb[i * 3 + 0];
        sy[i] = cb[i * 3 + 1];
        sz[i] = cb[i * 3 + 2];
    }
    __syncthreads();

    int qA = bidx * MF + chunk * 512 + threadIdx.x;
    int qB = qA + 256;
    float ax = qxyz[qA * 3 + 0], ay = qxyz[qA * 3 + 1], az = qxyz[qA * 3 + 2];
    float bx = qxyz[qB * 3 + 0], by = qxyz[qB * 3 + 1], bz = qxyz[qB * 3 + 2];

    float a0 = 1e30f, a1 = 1e30f, a2 = 1e30f; int ai0 = 0, ai1 = 0, ai2 = 0;
    float c0 = 1e30f, c1 = 1e30f, c2 = 1e30f; int ci0 = 0, ci1 = 0, ci2 = 0;

#pragma unroll 8
    for (int j = 0; j < NC; j++) {
        float px = sx[j], py = sy[j], pz = sz[j];
        {
            float dx = ax - px, dy = ay - py, dz = az - pz;
            float d = fmaf(dz, dz, fmaf(dy, dy, dx * dx));
            if (d < a2) {
                if (d < a1) {
                    a2 = a1; ai2 = ai1;
                    if (d < a0) { a1 = a0; ai1 = ai0; a0 = d; ai0 = j; }
                    else        { a1 = d;  ai1 = j; }
                } else { a2 = d; ai2 = j; }
            }
        }
        {
            float dx = bx - px, dy = by - py, dz = bz - pz;
            float d = fmaf(dz, dz, fmaf(dy, dy, dx * dx));
            if (d < c2) {
                if (d < c1) {
                    c2 = c1; ci2 = ci1;
                    if (d < c0) { c1 = c0; ci1 = ci0; c0 = d; ci0 = j; }
                    else        { c1 = d;  ci1 = j; }
                } else { c2 = d; ci2 = j; }
            }
        }
    }

    {
        float r0 = 1.0f / (sqrtf(a0) + 1e-8f);
        float r1 = 1.0f / (sqrtf(a1) + 1e-8f);
        float r2 = 1.0f / (sqrtf(a2) + 1e-8f);
        float rs = 1.0f / (r0 + r1 + r2);
        g_idx[qA * 3 + 0] = bidx * NC + ai0;
        g_idx[qA * 3 + 1] = bidx * NC + ai1;
        g_idx[qA * 3 + 2] = bidx * NC + ai2;
        g_wgt[qA * 3 + 0] = r0 * rs;
        g_wgt[qA * 3 + 1] = r1 * rs;
        g_wgt[qA * 3 + 2] = r2 * rs;
    }
    {
        float r0 = 1.0f / (sqrtf(c0) + 1e-8f);
        float r1 = 1.0f / (sqrtf(c1) + 1e-8f);
        float r2 = 1.0f / (sqrtf(c2) + 1e-8f);
        float rs = 1.0f / (r0 + r1 + r2);
        g_idx[qB * 3 + 0] = bidx * NC + ci0;
        g_idx[qB * 3 + 1] = bidx * NC + ci1;
        g_idx[qB * 3 + 2] = bidx * NC + ci2;
        g_wgt[qB * 3 + 0] = r0 * rs;
        g_wgt[qB * 3 + 1] = r1 * rs;
        g_wgt[qB * 3 + 2] = r2 * rs;
    }
}

// ---------------------------------------------------------------------------
// fp16 2-term warp-MMA GEMM:  C = (Ahi+Alo)[M,K] @ Wh[K,192] + b' (+ interp)
// CTA 128x64, 8 warps (4Mx2N), warp tile 32x32, BK=64, 2-stage cp.async.
// D = Ahi*W + Alo*W (W single fp16; A split exact to ~2^-22).
// ---------------------------------------------------------------------------
#define HA_HI  0
#define HA_LO  16384
#define HB     32768
#define HSTRIDE 40960
#define HSMEM   (2 * HSTRIDE)

template<int K, bool INTERP>
__global__ __launch_bounds__(256)
void mma_gemm16(const __half* __restrict__ Ahi, const __half* __restrict__ Alo,
                const __half* __restrict__ Wh, const float* __restrict__ bias,
                float* __restrict__ C)
{
    constexpr int KT = K / 64;
    extern __shared__ char smem_c[];

    const int t    = threadIdx.x;
    const int lane = t & 31;
    const int wid  = t >> 5;
    const int wm   = wid & 3;
    const int wn   = wid >> 2;
    const int m0   = blockIdx.y * 128;
    const int n0   = blockIdx.x * 64;
    const int g8   = lane >> 3, r8 = lane & 7;
    const uint32_t sm0 = smem_addr(smem_c);

    int arow[4], akc[4]; uint32_t aoff[4];
#pragma unroll
    for (int q = 0; q < 4; q++) {
        int c = t + 256 * q;
        arow[q] = c >> 3;
        akc[q]  = (c & 7) * 8;
        aoff[q] = sw128((uint32_t)(arow[q] * 128 + (c & 7) * 16));
    }
    int brow[2], bkc[2]; uint32_t boff[2];
#pragma unroll
    for (int q = 0; q < 2; q++) {
        int c = t + 256 * q;
        brow[q] = c >> 3;
        bkc[q]  = (c & 7) * 8;
        boff[q] = sw128((uint32_t)(brow[q] * 128 + (c & 7) * 16));
    }

    auto issue = [&](int stage, int k0) {
        uint32_t sb = sm0 + (uint32_t)stage * HSTRIDE;
#pragma unroll
        for (int q = 0; q < 4; q++) {
            long src = (long)(m0 + arow[q]) * K + k0 + akc[q];
            cp_async16(sb + HA_HI + aoff[q], Ahi + src);
            cp_async16(sb + HA_LO + aoff[q], Alo + src);
        }
#pragma unroll
        for (int q = 0; q < 2; q++) {
            long src = (long)(n0 + brow[q]) * K + k0 + bkc[q];
            cp_async16(sb + HB + boff[q], Wh + src);
        }
        cp_commit();
    };

    issue(0, 0);

    float d[2][4][4] = {};

#pragma unroll 1
    for (int kt = 0; kt < KT; kt++) {
        const int cur  = kt & 1;
        const bool more = (kt + 1 < KT);
        if (more) issue(cur ^ 1, (kt + 1) * 64);
        if (more) cp_wait1(); else cp_wait0();
        __syncthreads();

        const uint32_t sbase = sm0 + (uint32_t)cur * HSTRIDE;
#pragma unroll
        for (int ks = 0; ks < 4; ks++) {
            const int kb = ks * 16;
            uint32_t ah[2][4], al[2][4], bh[2][4];
#pragma unroll
            for (int mi = 0; mi < 2; mi++) {
                int row = wm * 32 + mi * 16 + (g8 & 1) * 8 + r8;
                int kc  = kb + (g8 >> 1) * 8;
                uint32_t ad = sbase + sw128((uint32_t)(row * 128 + kc * 2));
                ldsm4(ah[mi], ad + HA_HI);
                ldsm4(al[mi], ad + HA_LO);
            }
#pragma unroll
            for (int ni = 0; ni < 2; ni++) {
                int row = wn * 32 + ni * 16 + (g8 >> 1) * 8 + r8;
                int kc  = kb + (g8 & 1) * 8;
                uint32_t bd = sbase + sw128((uint32_t)(row * 128 + kc * 2));
                ldsm4(bh[ni], bd + HB);
            }
#pragma unroll
            for (int mi = 0; mi < 2; mi++)
#pragma unroll
                for (int ni = 0; ni < 2; ni++)
#pragma unroll
                    for (int h = 0; h < 2; h++) {
                        float* acc = d[mi][ni * 2 + h];
                        mma16816h(acc, ah[mi], &bh[ni][h * 2]);
                        mma16816h(acc, al[mi], &bh[ni][h * 2]);
                    }
        }
        if (more) __syncthreads();
    }

    // --- epilogue: bias (+ fused interp gather)
    const int lr = lane >> 2;
    const int lc = (lane & 3) * 2;
#pragma unroll
    for (int mi = 0; mi < 2; mi++) {
#pragma unroll
        for (int half = 0; half < 2; half++) {
            int row = m0 + wm * 32 + mi * 16 + lr + half * 8;
            int j0 = 0, j1 = 0, j2 = 0;
            float w0 = 0.f, w1 = 0.f, w2 = 0.f;
            if (INTERP) {
                j0 = g_idx[row * 3 + 0]; j1 = g_idx[row * 3 + 1]; j2 = g_idx[row * 3 + 2];
                w0 = g_wgt[row * 3 + 0]; w1 = g_wgt[row * 3 + 1]; w2 = g_wgt[row * 3 + 2];
            }
            float* crow = C + (long)row * COUT;
#pragma unroll
            for (int nt = 0; nt < 4; nt++) {
                int col = n0 + wn * 32 + nt * 8 + lc;
                float vx = d[mi][nt][half * 2 + 0] + bias[col + 0];
                float vy = d[mi][nt][half * 2 + 1] + bias[col + 1];
                if (INTERP) {
                    float2 h0 = *(const float2*)(g_h + (long)j0 * COUT + col);
                    float2 h1 = *(const float2*)(g_h + (long)j1 * COUT + col);
                    float2 h2 = *(const float2*)(g_h + (long)j2 * COUT + col);
                    vx += w0 * h0.x + w1 * h1.x + w2 * h2.x;
                    vy += w0 * h0.y + w1 * h1.y + w2 * h2.y;
                }
                *(float2*)(crow + col) = make_float2(vx, vy);
            }
        }
    }
}

// ---------------------------------------------------------------------------
// Tail: copy support_xyz and support_offset (value-cast to float) into d_out
// ---------------------------------------------------------------------------
__global__ void tail_kernel(const float* __restrict__ sxyz, const int* __restrict__ soff,
                            float* __restrict__ out)
{
    int i = blockIdx.x * 256 + threadIdx.x;
    if (i < MTOT * 3) out[MTOT * COUT + i] = sxyz[i];
    if (i < B_)       out[MTOT * COUT + MTOT * 3 + i] = (float)soff[i];
}

// ---------------------------------------------------------------------------
extern "C" void kernel_launch(void* const* d_in, const int* in_sizes, int n_in,
                              void* d_out, int out_size)
{
    const float* feats  = (const float*)d_in[0];
    const float* xyz    = (const float*)d_in[1];
    const float* sxyz   = (const float*)d_in[2];
    const float* sfeats = (const float*)d_in[3];
    const int*   soff   = (const int*)  d_in[5];
    const float* ln1_g  = (const float*)d_in[6];
    const float* ln1_b  = (const float*)d_in[7];
    const float* w1     = (const float*)d_in[8];
    const float* b1     = (const float*)d_in[9];
    const float* ln2_g  = (const float*)d_in[10];
    const float* ln2_b  = (const float*)d_in[11];
    const float* w2     = (const float*)d_in[12];
    const float* b2     = (const float*)d_in[13];
    float* out = (float*)d_out;

    static cudaStream_t s2 = nullptr, s3 = nullptr;
    static cudaEvent_t ev_fork = nullptr, ev_j2 = nullptr, ev_j3 = nullptr, ev_prep = nullptr;
    static bool attr_done = false;
    if (!s2) {
        cudaStreamCreateWithFlags(&s2, cudaStreamNonBlocking);
        cudaStreamCreateWithFlags(&s3, cudaStreamNonBlocking);
        cudaEventCreateWithFlags(&ev_fork, cudaEventDisableTiming);
        cudaEventCreateWithFlags(&ev_j2, cudaEventDisableTiming);
        cudaEventCreateWithFlags(&ev_j3, cudaEventDisableTiming);
        cudaEventCreateWithFlags(&ev_prep, cudaEventDisableTiming);
    }
    if (!attr_done) {
        cudaFuncSetAttribute(mma_gemm16<CIN,  false>, cudaFuncAttributeMaxDynamicSharedMemorySize, HSMEM);
        cudaFuncSetAttribute(mma_gemm16<COUT, true >, cudaFuncAttributeMaxDynamicSharedMemorySize, HSMEM);
        attr_done = true;
    }

    float *p_h, *p_b2p, *p_b1p;
    __half *p_fhi, *p_flo, *p_shi, *p_slo, *p_w2h, *p_w1h;
    cudaGetSymbolAddress((void**)&p_h,    g_h);
    cudaGetSymbolAddress((void**)&p_b2p,  g_b2p);
    cudaGetSymbolAddress((void**)&p_b1p,  g_b1p);
    cudaGetSymbolAddress((void**)&p_fhi,  g_fhi);
    cudaGetSymbolAddress((void**)&p_flo,  g_flo);
    cudaGetSymbolAddress((void**)&p_shi,  g_shi);
    cudaGetSymbolAddress((void**)&p_slo,  g_slo);
    cudaGetSymbolAddress((void**)&p_w2h,  g_w2h);
    cudaGetSymbolAddress((void**)&p_w1h,  g_w1h);

    // fork
    cudaEventRecord(ev_fork, 0);
    cudaStreamWaitEvent(s2, ev_fork, 0);
    cudaStreamWaitEvent(s3, ev_fork, 0);

    // s2: kNN + tail (fills scheduling gaps of the main chain)
    knn_kernel<<<MTOT / 512, 256, 3 * NC * sizeof(float), s2>>>(xyz, sxyz);
    tail_kernel<<<(MTOT * 3 + 255) / 256, 256, 0, s2>>>(sxyz, soff, out);
    cudaEventRecord(ev_j2, s2);

    // s3: weight prep, then sfeats fp16 conversion (needed only by gemm1)
    prep_kernel<<<2 * COUT + 2, COUT, 0, s3>>>(w2, ln2_g, ln2_b, b2, w1, ln1_g, ln1_b, b1);
    cudaEventRecord(ev_prep, s3);
    stats_conv16_kernel<COUT><<<MTOT / 8, 256, 0, s3>>>(sfeats, p_shi, p_slo, MTOT);
    cudaEventRecord(ev_j3, s3);

    // main: feats conversion -> gemm2 (fp16 2-term mma) -> g_h
    stats_conv16_kernel<CIN><<<NTOT / 8, 256>>>(feats, p_fhi, p_flo, NTOT);
    cudaStreamWaitEvent(0, ev_prep, 0);
    {
        dim3 grid(COUT / 64, NTOT / 128);
        mma_gemm16<CIN, false><<<grid, 256, HSMEM>>>(p_fhi, p_flo, p_w2h, p_b2p, p_h);
    }

    // join, then gemm1 (fp16 2-term mma) with fused interp epilogue
    cudaStreamWaitEvent(0, ev_j2, 0);
    cudaStreamWaitEvent(0, ev_j3, 0);
    {
        dim3 grid(COUT / 64, MTOT / 128);
        mma_gemm16<COUT, true><<<grid, 256, HSMEM>>>(p_shi, p_slo, p_w1h, p_b1p, out);
    }
}